// round 1
// baseline (speedup 1.0000x reference)
#include <cuda_runtime.h>
#include <cuda_bf16.h>
#include <cstdint>

// Problem constants (CTC_72000831750194): B=32, T=1000, V=1024, L=128
#define CB 32
#define CT 1000
#define CV 1024
#define CL 128
#define CS (2 * CL + 1)   // 257
#define NEG (-1e30f)

// Scratch (allocation-free rule: __device__ globals)
__device__ float g_lp[(size_t)CB * CT * CS];   // gathered log-probs at extended labels
__device__ float g_loss[CB];                   // per-batch loss / ys_len

// ---------------------------------------------------------------------------
// Kernel 1: per-(b,t) logsumexp over V, then gather 257 extended-label probs.
// grid = B*T blocks, 256 threads. V/4 = 256 -> one float4 per thread.
// ---------------------------------------------------------------------------
__global__ void __launch_bounds__(256) ctc_lp_kernel(
    const float* __restrict__ hs, const int* __restrict__ ys)
{
    const int bt  = blockIdx.x;
    const int b   = bt / CT;
    const int tid = threadIdx.x;

    const float* row = hs + (size_t)bt * CV;
    const float4 v = reinterpret_cast<const float4*>(row)[tid];

    // --- block max ---
    float m = fmaxf(fmaxf(v.x, v.y), fmaxf(v.z, v.w));
    #pragma unroll
    for (int o = 16; o > 0; o >>= 1)
        m = fmaxf(m, __shfl_xor_sync(0xffffffffu, m, o));

    __shared__ float red_m[8];
    __shared__ float red_s[8];
    if ((tid & 31) == 0) red_m[tid >> 5] = m;
    __syncthreads();
    float bm = red_m[0];
    #pragma unroll
    for (int i = 1; i < 8; ++i) bm = fmaxf(bm, red_m[i]);

    // --- block sum of exp ---
    float s = __expf(v.x - bm) + __expf(v.y - bm) +
              __expf(v.z - bm) + __expf(v.w - bm);
    #pragma unroll
    for (int o = 16; o > 0; o >>= 1)
        s += __shfl_xor_sync(0xffffffffu, s, o);
    if ((tid & 31) == 0) red_s[tid >> 5] = s;
    __syncthreads();
    float tot = red_s[0];
    #pragma unroll
    for (int i = 1; i < 8; ++i) tot += red_s[i];

    const float lse = bm + __logf(tot);

    // --- gather extended-label log-probs ---
    // ext[s] = 0 (blank) for even s, ys[b][(s-1)/2] for odd s.
    float* out = g_lp + (size_t)bt * CS;
    for (int si = tid; si < CS; si += 256) {
        const int lab = (si & 1) ? ys[b * CL + (si >> 1)] : 0;
        out[si] = row[lab] - lse;   // L1-hot: the whole 4KB row was just read
    }
}

// branchless log-add-exp of 3 terms (terms at NEG contribute exp()=0 exactly
// in the sense that exp(NEG - m) underflows to 0 for any finite m)
__device__ __forceinline__ float lad3(float a, float b, float c)
{
    float m = fmaxf(fmaxf(a, b), c);
    float s = __expf(a - m) + __expf(b - m) + __expf(c - m);
    return m + __logf(s);
}
__device__ __forceinline__ float lad2(float a, float b)
{
    float m = fmaxf(a, b);
    float s = __expf(a - m) + __expf(b - m);
    return m + __logf(s);
}

// ---------------------------------------------------------------------------
// Kernel 2: sequential alpha recursion. One block per batch element.
// 256 threads: thread tid owns lattice state s=tid; thread 0 also owns s=256.
// Double-buffered smem alpha (padded by 2 NEG at the front) -> 1 barrier/step.
// lp for step t+1 is prefetched into registers before the barrier.
// ---------------------------------------------------------------------------
__global__ void __launch_bounds__(256) ctc_alpha_kernel(
    const int* __restrict__ h_lens, const int* __restrict__ ys,
    const int* __restrict__ ys_lens)
{
    __shared__ float buf[2][CS + 3];   // [pad0 pad1 | alpha[0..S-1]]

    const int b   = blockIdx.x;
    const int tid = threadIdx.x;
    const int Tb  = h_lens[b];
    const float* lpb = g_lp + (size_t)b * CT * CS;

    // static pads (never overwritten; writes go to indices >= 2)
    if (tid < 2) { buf[0][tid] = NEG; buf[1][tid] = NEG; }

    // alpha at t=0: states 0 and 1 live, everything else NEG
    buf[0][tid + 2] = (tid <= 1) ? lpb[tid] : NEG;
    if (tid == 0) buf[0][256 + 2] = NEG;

    // skip mask: only odd s >= 3, and consecutive labels differ
    const bool skip0 = (tid & 1) && (tid >= 3) &&
                       (ys[b * CL + (tid >> 1)] != ys[b * CL + (tid >> 1) - 1]);
    // s = 256 is even (blank) -> never skip, lad2 only.

    float lp_cur  = (Tb > 1) ? lpb[CS + tid] : 0.f;
    float lp_cur2 = (tid == 0 && Tb > 1) ? lpb[CS + 256] : 0.f;
    __syncthreads();

    int p = 0;
    for (int t = 1; t < Tb; ++t) {
        // prefetch next step's lp while this step computes
        const float* nxt = lpb + (size_t)(t + 1) * CS;
        const bool   hasn = (t + 1 < Tb);
        float lp_n  = hasn ? nxt[tid] : 0.f;
        float lp_n2 = (tid == 0 && hasn) ? nxt[256] : 0.f;

        const float* rd = buf[p];
        float*       wr = buf[p ^ 1];

        const float a1 = rd[tid + 2];
        const float a2 = rd[tid + 1];
        const float a3 = skip0 ? rd[tid] : NEG;
        wr[tid + 2] = lad3(a1, a2, a3) + lp_cur;

        if (tid == 0) {   // state s = 256 (final blank): no skip transition
            wr[256 + 2] = lad2(rd[256 + 2], rd[256 + 1]) + lp_cur2;
        }
        __syncthreads();
        lp_cur  = lp_n;
        lp_cur2 = lp_n2;
        p ^= 1;
    }

    if (tid == 0) {
        const int   yl = ys_lens[b];
        const float ab = buf[p][2 * yl + 2];       // final blank
        const float al = buf[p][2 * yl - 1 + 2];   // final label
        g_loss[b] = -lad2(ab, al) / (float)yl;
    }
}

// ---------------------------------------------------------------------------
// Kernel 3: mean over batch -> scalar output
// ---------------------------------------------------------------------------
__global__ void ctc_reduce_kernel(float* __restrict__ out)
{
    float v = (threadIdx.x < CB) ? g_loss[threadIdx.x] : 0.f;
    #pragma unroll
    for (int o = 16; o > 0; o >>= 1)
        v += __shfl_xor_sync(0xffffffffu, v, o);
    if (threadIdx.x == 0) out[0] = v / (float)CB;
}

extern "C" void kernel_launch(void* const* d_in, const int* in_sizes, int n_in,
                              void* d_out, int out_size)
{
    const float* hs      = (const float*)d_in[0];  // (B, T, V)
    const int*   h_lens  = (const int*)  d_in[1];  // (B,)
    const int*   ys      = (const int*)  d_in[2];  // (B, L)
    const int*   ys_lens = (const int*)  d_in[3];  // (B,)
    float*       out     = (float*)      d_out;

    ctc_lp_kernel<<<CB * CT, 256>>>(hs, ys);
    ctc_alpha_kernel<<<CB, 256>>>(h_lens, ys, ys_lens);
    ctc_reduce_kernel<<<1, 32>>>(out);
}